// round 8
// baseline (speedup 1.0000x reference)
#include <cuda_runtime.h>
#include <cuda_bf16.h>
#include <math.h>
#include <stdint.h>

#define BB 2
#define LL 2048
#define DD 1024
#define HH 16
#define HDIM 64
#define D3 3072
#define RLEN 4095   // 2*L - 1
#define MTOT 4096   // B*L
#define K2 2048     // hi|lo concatenated K

// Scratch (no allocation allowed)
__device__ float g_scores[HH * RLEN];
__device__ __align__(1024) __nv_bfloat16 g_Abig[(size_t)MTOT * K2];  // x  hi|lo
__device__ __align__(1024) __nv_bfloat16 g_Bbig[(size_t)D3 * K2];    // w  hi|lo
// Per-head bf16 hi/lo tensors: [b][h][l][64]
#define HSZ ((size_t)BB * HH * LL * HDIM)
__device__ __align__(1024) __nv_bfloat16 g_Qh[HSZ];
__device__ __align__(1024) __nv_bfloat16 g_Ql[HSZ];
__device__ __align__(1024) __nv_bfloat16 g_Kh[HSZ];
__device__ __align__(1024) __nv_bfloat16 g_Kl[HSZ];
__device__ __align__(1024) __nv_bfloat16 g_Vh[HSZ];
__device__ __align__(1024) __nv_bfloat16 g_Vl[HSZ];

__device__ __forceinline__ uint32_t smem_to_u32(const void* p) {
    uint32_t a;
    asm("{ .reg .u64 t; cvta.to.shared.u64 t, %1; cvt.u32.u64 %0, t; }"
        : "=r"(a) : "l"(p));
    return a;
}
#define CP16(dst, src) \
    asm volatile("cp.async.cg.shared.global [%0], [%1], 16;" :: "r"(dst), "l"(src))
#define CP_COMMIT() asm volatile("cp.async.commit_group;" ::: "memory")
#define CP_WAITG(n) asm volatile("cp.async.wait_group %0;" :: "n"(n) : "memory")

__device__ __forceinline__ void ldsm4(uint32_t* r, uint32_t addr) {
    asm volatile("ldmatrix.sync.aligned.m8n8.x4.shared.b16 {%0, %1, %2, %3}, [%4];"
                 : "=r"(r[0]), "=r"(r[1]), "=r"(r[2]), "=r"(r[3]) : "r"(addr));
}
__device__ __forceinline__ void ldsm4t(uint32_t* r, uint32_t addr) {
    asm volatile("ldmatrix.sync.aligned.m8n8.x4.trans.shared.b16 {%0, %1, %2, %3}, [%4];"
                 : "=r"(r[0]), "=r"(r[1]), "=r"(r[2]), "=r"(r[3]) : "r"(addr));
}
__device__ __forceinline__ void mma16816(float* c, const uint32_t* a, const uint32_t* b) {
    asm volatile("mma.sync.aligned.m16n8k16.row.col.f32.bf16.bf16.f32 "
                 "{%0, %1, %2, %3}, {%4, %5, %6, %7}, {%8, %9}, {%0, %1, %2, %3};"
                 : "+f"(c[0]), "+f"(c[1]), "+f"(c[2]), "+f"(c[3])
                 : "r"(a[0]), "r"(a[1]), "r"(a[2]), "r"(a[3]), "r"(b[0]), "r"(b[1]));
}
// packed bf16x2: low = lo, high = hi
__device__ __forceinline__ uint32_t packbf(float lo, float hi) {
    uint32_t r;
    asm("cvt.rn.bf16x2.f32 %0, %1, %2;" : "=r"(r) : "f"(hi), "f"(lo));
    return r;
}
// 64B-row (BK=32) swizzle: row pairs share one 128B line, 8 distinct 16B cols
__device__ __forceinline__ uint32_t sw32(uint32_t base, int row, int kseg) {
    uint32_t col = (uint32_t)((((row & 1) << 2) | kseg) ^ ((row >> 1) & 7));
    return base + ((uint32_t)(row >> 1) << 7) + (col << 4);
}

// ---------------------------------------------------------------------------
// Kernel 1: TISA bias table (grid 16 x 8 for full-chip spread)
// ---------------------------------------------------------------------------
__global__ __launch_bounds__(256) void scores_kernel(const float* __restrict__ off,
                                                     const float* __restrict__ amp,
                                                     const float* __restrict__ shp)
{
    int h = blockIdx.x;
    __shared__ float so[16], sa[16], ss[16];
    if (threadIdx.x < 16) {
        so[threadIdx.x] = off[h * 16 + threadIdx.x];
        sa[threadIdx.x] = amp[h * 16 + threadIdx.x];
        ss[threadIdx.x] = fabsf(shp[h * 16 + threadIdx.x]);
    }
    __syncthreads();
    for (int r = blockIdx.y * 256 + threadIdx.x; r < RLEN; r += 8 * 256) {
        float rel = (float)(r - (LL - 1));
        float acc = 0.f;
#pragma unroll
        for (int k = 0; k < 16; k++) {
            float d = so[k] - rel;
            acc += sa[k] * expf(-ss[k] * d * d);
        }
        g_scores[h * RLEN + r] = acc;
    }
}

// ---------------------------------------------------------------------------
// Kernel 2a: fused fp32 -> bf16 hi/lo split for x and w_in (single launch)
// ---------------------------------------------------------------------------
__global__ __launch_bounds__(256) void convert2_kernel(const float* __restrict__ x,
                                                       const float* __restrict__ w)
{
    int idx = blockIdx.x * 256 + threadIdx.x;
    int row = idx >> 8;
    int k = (idx & 255) << 2;
    const float* src;
    __nv_bfloat16* dst;
    int r;
    if (row < MTOT) { src = x; dst = g_Abig; r = row; }
    else            { src = w; dst = g_Bbig; r = row - MTOT; }
    float4 v = *(const float4*)(src + (size_t)r * DD + k);
    __nv_bfloat16 h0 = __float2bfloat16_rn(v.x);
    __nv_bfloat16 h1 = __float2bfloat16_rn(v.y);
    __nv_bfloat16 h2 = __float2bfloat16_rn(v.z);
    __nv_bfloat16 h3 = __float2bfloat16_rn(v.w);
    __nv_bfloat16 l0 = __float2bfloat16_rn(v.x - __bfloat162float(h0));
    __nv_bfloat16 l1 = __float2bfloat16_rn(v.y - __bfloat162float(h1));
    __nv_bfloat16 l2 = __float2bfloat16_rn(v.z - __bfloat162float(h2));
    __nv_bfloat16 l3 = __float2bfloat16_rn(v.w - __bfloat162float(h3));
    __nv_bfloat162* dh = (__nv_bfloat162*)(dst + (size_t)r * K2 + k);
    dh[0] = __nv_bfloat162(h0, h1);
    dh[1] = __nv_bfloat162(h2, h3);
    __nv_bfloat162* dl = (__nv_bfloat162*)(dst + (size_t)r * K2 + DD + k);
    dl[0] = __nv_bfloat162(l0, l1);
    dl[1] = __nv_bfloat162(l2, l3);
}

// ---------------------------------------------------------------------------
// Kernel 2b: HMMA split GEMM, merged 3-product chunks.
// CTA 128x128, 8 warps (4M x 2N), warp tile 32x64, BK=32.
// Stage (32KB): Ahi 8K | Alo 8K | Bhi 8K | Blo 8K. 3-stage cp.async.
// Per chunk: Ahi*Bhi + Alo*Bhi + Ahi*Blo, all into one fp32 acc.
// 2 CTAs/SM (96KB smem, <=128 regs).
// ---------------------------------------------------------------------------
#define PCHUNK 32
#define PSTG 32768

__device__ __forceinline__ void load_chunk_p(uint32_t stg, int bm, int bn,
                                             int kc, int tid)
{
#pragma unroll
    for (int i = 0; i < 8; i++) {
        const int comp = i >> 1;
        int s = tid + (i & 1) * 256;      // 0..511 per component
        int row = s >> 2, kseg = s & 3;
        uint32_t dst = sw32(stg + comp * 8192, row, kseg);
        const void* src;
        if (comp == 0)
            src = g_Abig + (size_t)(bm + row) * K2 + kc + kseg * 8;
        else if (comp == 1)
            src = g_Abig + (size_t)(bm + row) * K2 + DD + kc + kseg * 8;
        else if (comp == 2)
            src = g_Bbig + (size_t)(bn + row) * K2 + kc + kseg * 8;
        else
            src = g_Bbig + (size_t)(bn + row) * K2 + DD + kc + kseg * 8;
        CP16(dst, src);
    }
    CP_COMMIT();
}

__global__ __launch_bounds__(256, 2) void proj_mma()
{
    extern __shared__ char smem[];
    const uint32_t sbase = smem_to_u32(smem);
    const int tid = threadIdx.x;
    const int wid = tid >> 5, lane = tid & 31;
    const int bm = blockIdx.y * 128, bn = blockIdx.x * 128;
    const int wm = (wid >> 1) * 32;
    const int wn = (wid & 1) * 64;

    float acc[2][8][4];
#pragma unroll
    for (int mt = 0; mt < 2; mt++)
#pragma unroll
        for (int nt = 0; nt < 8; nt++)
#pragma unroll
            for (int c = 0; c < 4; c++) acc[mt][nt][c] = 0.f;

    load_chunk_p(sbase, bm, bn, 0, tid);
    load_chunk_p(sbase + PSTG, bm, bn, 32, tid);

    for (int t = 0; t < PCHUNK; t++) {
        CP_WAITG(1);
        __syncthreads();

        if (t + 2 < PCHUNK) {
            load_chunk_p(sbase + ((t + 2) % 3) * PSTG, bm, bn, (t + 2) * 32, tid);
        } else {
            CP_COMMIT();
        }

        const uint32_t sAh = sbase + (t % 3) * PSTG;
        const uint32_t sAl = sAh + 8192;
        const uint32_t sBh = sAh + 16384;
        const uint32_t sBl = sAh + 24576;

#pragma unroll
        for (int kk = 0; kk < 2; kk++) {
            uint32_t aH[2][4], aL[2][4];
#pragma unroll
            for (int mt = 0; mt < 2; mt++) {
                int row = wm + mt * 16 + (lane & 15);
                int kseg = kk * 2 + (lane >> 4);
                ldsm4(aH[mt], sw32(sAh, row, kseg));
                ldsm4(aL[mt], sw32(sAl, row, kseg));
            }
            uint32_t b[8][2];
            int brow = (lane & 7) + ((lane >> 4) << 3);
            int bkseg = kk * 2 + ((lane >> 3) & 1);
#pragma unroll
            for (int p = 0; p < 4; p++) {
                int row = wn + p * 16 + brow;
                ldsm4(&b[2 * p][0], sw32(sBh, row, bkseg));
            }
#pragma unroll
            for (int mt = 0; mt < 2; mt++)
#pragma unroll
                for (int nt = 0; nt < 8; nt++) {
                    mma16816(acc[mt][nt], aH[mt], b[nt]);
                    mma16816(acc[mt][nt], aL[mt], b[nt]);
                }
#pragma unroll
            for (int p = 0; p < 4; p++) {
                int row = wn + p * 16 + brow;
                ldsm4(&b[2 * p][0], sw32(sBl, row, bkseg));
            }
#pragma unroll
            for (int mt = 0; mt < 2; mt++)
#pragma unroll
                for (int nt = 0; nt < 8; nt++)
                    mma16816(acc[mt][nt], aH[mt], b[nt]);
        }
        __syncthreads();
    }

    // Epilogue: split each value into bf16 hi/lo, write to per-head q/k/v arrays.
#pragma unroll
    for (int mt = 0; mt < 2; mt++) {
        int row0 = bm + wm + mt * 16 + (lane >> 2);
        int b = row0 >> 11;
        int l = row0 & 2047;
#pragma unroll
        for (int nt = 0; nt < 8; nt++) {
            int col = bn + wn + nt * 8 + (lane & 3) * 2;
            int ty = col >> 10;            // 0=k, 1=v, 2=q
            int h = (col >> 6) & 15;
            int d = col & 63;
            float sc = (ty == 2) ? 0.125f : 1.0f;
            float v0 = acc[mt][nt][0] * sc, v1 = acc[mt][nt][1] * sc;
            float v2 = acc[mt][nt][2] * sc, v3 = acc[mt][nt][3] * sc;
            uint32_t h01 = packbf(v0, v1), h23 = packbf(v2, v3);
            uint32_t l01 = packbf(v0 - __uint_as_float(h01 << 16),
                                  v1 - __uint_as_float(h01 & 0xFFFF0000u));
            uint32_t l23 = packbf(v2 - __uint_as_float(h23 << 16),
                                  v3 - __uint_as_float(h23 & 0xFFFF0000u));
            __nv_bfloat16 *dh, *dl;
            if (ty == 0)      { dh = g_Kh; dl = g_Kl; }
            else if (ty == 1) { dh = g_Vh; dl = g_Vl; }
            else              { dh = g_Qh; dl = g_Ql; }
            size_t base0 = ((size_t)(b * HH + h) * LL + l) * HDIM + d;
            size_t base1 = base0 + 8 * HDIM;
            *(uint32_t*)(dh + base0) = h01;
            *(uint32_t*)(dl + base0) = l01;
            *(uint32_t*)(dh + base1) = h23;
            *(uint32_t*)(dl + base1) = l23;
        }
    }
}

// ---------------------------------------------------------------------------
// Kernel 3: HMMA flash attention, hi/lo split, 2 CTAs/SM. (unchanged from R6)
// smem: KV stage s at s*32768 (Khi|Klo|Vhi|Vlo, 8KB each);
//       Q dedicated @65536 (hi 16KB, lo 16KB); bias sb[2][192] @98304.
// ---------------------------------------------------------------------------
__device__ __forceinline__ void attn_load_k(uint32_t sbase, int stage, int bh,
                                            int kb, int tid)
{
    uint32_t stg = sbase + stage * 32768;
#pragma unroll
    for (int i = 0; i < 4; i++) {
        const int comp = i >> 1;           // 0=Khi 1=Klo
        int row = (tid >> 3) + 32 * (i & 1);
        int kseg = tid & 7;
        const __nv_bfloat16* gb = comp ? g_Kl : g_Kh;
        uint32_t dst = stg + comp * 8192 + row * 128 + ((kseg ^ (row & 7)) << 4);
        const void* src = gb + ((size_t)bh * LL + kb + row) * HDIM + kseg * 8;
        CP16(dst, src);
    }
    CP_COMMIT();
}
__device__ __forceinline__ void attn_load_v(uint32_t sbase, int stage, int bh,
                                            int kb, int tid)
{
    uint32_t stg = sbase + stage * 32768 + 16384;
#pragma unroll
    for (int i = 0; i < 4; i++) {
        const int comp = i >> 1;           // 0=Vhi 1=Vlo
        int row = (tid >> 3) + 32 * (i & 1);
        int kseg = tid & 7;
        const __nv_bfloat16* gb = comp ? g_Vl : g_Vh;
        uint32_t dst = stg + comp * 8192 + row * 128 + ((kseg ^ (row & 7)) << 4);
        const void* src = gb + ((size_t)bh * LL + kb + row) * HDIM + kseg * 8;
        CP16(dst, src);
    }
    CP_COMMIT();
}

__global__ __launch_bounds__(256, 2) void attn_mma(float* __restrict__ out)
{
    extern __shared__ char smem[];
    const uint32_t sbase = smem_to_u32(smem);
    const uint32_t sQ = sbase + 65536;     // Q hi @ +0, Q lo @ +16384
    float* sb = (float*)(smem + 98304);    // [2][192]
    const int tid = threadIdx.x;
    const int wid = tid >> 5, lane = tid & 31;
    const int gid = lane >> 2, tg = lane & 3;
    const int qb = blockIdx.x * 128;
    const int h = blockIdx.y, b = blockIdx.z;
    const int bh = b * HH + h;
    const int wm = wid * 16;
    const float* srow = g_scores + h * RLEN;

    // --- Prologue: Q (hi/lo) into dedicated smem; K0/V0 issued right behind.
#pragma unroll
    for (int i = 0; i < 8; i++) {
        const int comp = i >> 2;
        int row = (tid >> 3) + 32 * (i & 3);
        int kseg = tid & 7;
        const __nv_bfloat16* gb = comp ? g_Ql : g_Qh;
        uint32_t dst = sQ + comp * 16384 + row * 128 + ((kseg ^ (row & 7)) << 4);
        const void* src = gb + ((size_t)bh * LL + qb + row) * HDIM + kseg * 8;
        CP16(dst, src);
    }
    CP_COMMIT();                         // group: Q
    attn_load_k(sbase, 0, bh, 0, tid);   // group: K0
    attn_load_v(sbase, 0, bh, 0, tid);   // group: V0
    if (tid < 192) {
        int sidx = qb + 1984 + tid;
        sb[tid] = srow[min(sidx, RLEN - 1)];
    }
    CP_WAITG(2);                         // Q done (K0/V0 may be pending)
    __syncthreads();

    uint32_t aQh[4][4];
#pragma unroll
    for (int ks = 0; ks < 4; ks++) {
        int row = wm + (lane & 15);
        int kseg = ks * 2 + (lane >> 4);
        ldsm4(aQh[ks], sQ + row * 128 + ((kseg ^ (row & 7)) << 4));
    }

    float O[8][4];
#pragma unroll
    for (int nt = 0; nt < 8; nt++)
#pragma unroll
        for (int c = 0; c < 4; c++) O[nt][c] = 0.f;
    float m0 = -1e30f, m1 = -1e30f, l0 = 0.f, l1 = 0.f;

    for (int t = 0; t < LL / 64; t++) {
        // pending here: K(t), V(t). Wait K only.
        CP_WAITG(1);
        __syncthreads();
        const uint32_t stg = sbase + (t & 1) * 32768;
        const float* sbt = sb + (t & 1) * 192;

        if (t + 1 < LL / 64) {
            attn_load_k(sbase, (t + 1) & 1, bh, (t + 1) * 64, tid);
            attn_load_v(sbase, (t + 1) & 1, bh, (t + 1) * 64, tid);
            if (tid < 192) {
                int sidx = qb - (t + 1) * 64 + 1984 + tid;
                sb[((t + 1) & 1) * 192 + tid] = srow[min(sidx, RLEN - 1)];
            }
        } else {
            CP_COMMIT();
            CP_COMMIT();
        }

        // ---- S = Q K^T (3-pass split), fp32 accum
        float S[8][4];
#pragma unroll
        for (int nt = 0; nt < 8; nt++)
#pragma unroll
            for (int c = 0; c < 4; c++) S[nt][c] = 0.f;

#pragma unroll
        for (int kk = 0; kk < 4; kk++) {
            // Q-lo fragment for this k-step (from dedicated smem)
            uint32_t aQl[4];
            {
                int row = wm + (lane & 15);
                int kseg = kk * 2 + (lane >> 4);
                ldsm4(aQl, sQ + 16384 + row * 128 + ((kseg ^ (row & 7)) << 4));
            }
            uint32_t kf[8][2];
            int krow = (lane & 7) + ((lane >> 4) << 3);
            int kkseg = kk * 2 + ((lane >> 3) & 1);
#pragma unroll
            for (int p = 0; p < 4; p++) {
                int row = krow + p * 16;
                uint32_t addr = stg + row * 128 + ((kkseg ^ (row & 7)) << 4);
                ldsm4(&kf[2 * p][0], addr);
            }
#pragma unroll
            for (int nt = 0; nt < 8; nt++) {
                mma16816(S[nt], aQh[kk], kf[nt]);
                mma16816(S[nt], aQl, kf[nt]);
            }
#pragma unroll
            for (int p = 0; p < 4; p++) {
                int row = krow + p * 16;
                uint32_t addr = stg + 8192 + row * 128 + ((kkseg ^ (row & 7)) << 4);
                ldsm4(&kf[2 * p][0], addr);
            }
#pragma unroll
            for (int nt = 0; nt < 8; nt++)
                mma16816(S[nt], aQh[kk], kf[nt]);
        }

        // ---- bias + online softmax (V load still in flight underneath)
        const int jbase = wm + gid + 63 - 2 * tg;
        float mx0 = -1e30f, mx1 = -1e30f;
#pragma unroll
        for (int nt = 0; nt < 8; nt++) {
            int j = jbase - 8 * nt;
            S[nt][0] += sbt[j];
            S[nt][1] += sbt[j - 1];
            S[nt][2] += sbt[j + 8];
            S[nt][3] += sbt[j + 7];
            mx0 = fmaxf(mx0, fmaxf(S[nt][0], S[nt][1]));
            mx1 = fmaxf(mx1, fmaxf(S[nt][2], S[nt][3]));
        }
        mx0 = fmaxf(mx0, __shfl_xor_sync(0xffffffffu, mx0, 1));
        mx0 = fmaxf(mx0, __shfl_xor_sync(0xffffffffu, mx0, 2));
        mx1 = fmaxf(mx1, __shfl_xor_sync(0xffffffffu, mx1, 1));
        mx1 = fmaxf(mx1, __shfl_xor_sync(0xffffffffu, mx1, 2));
        float nm0 = fmaxf(m0, mx0), nm1 = fmaxf(m1, mx1);
        float c0 = __expf(m0 - nm0), c1 = __expf(m1 - nm1);
        m0 = nm0; m1 = nm1;

        float rs0 = 0.f, rs1 = 0.f;
        uint32_t aPh[4][4], aPl[4][4];
#pragma unroll
        for (int nt = 0; nt < 8; nt++) {
            float p0 = __expf(S[nt][0] - nm0);
            float p1 = __expf(S[nt][1] - nm0);
            float p2 = __expf(S[nt][2] - nm1);
            float p3 = __expf(S[nt][3] - nm1);
            rs0 += p0 + p1;
            rs1 += p2 + p3;
            uint32_t h01 = packbf(p0, p1), h23 = packbf(p2, p3);
            uint32_t l01 = packbf(p0 - __uint_as_float(h01 << 16),
                                  p1 - __uint_as_float(h01 & 0xFFFF0000u));
            uint32_t l23 = packbf(p2 - __uint_as_float(h23 << 16),
                                  p3 - __uint_as_float(h23 & 0xFFFF0000u));
            int ks = nt >> 1, hf = (nt & 1) * 2;
            aPh[ks][hf] = h01; aPh[ks][hf + 1] = h23;
            aPl[ks][hf] = l01; aPl[ks][hf + 1] = l23;
        }
        rs0 += __shfl_xor_sync(0xffffffffu, rs0, 1);
        rs0 += __shfl_xor_sync(0xffffffffu, rs0, 2);
        rs1 += __shfl_xor_sync(0xffffffffu, rs1, 1);
        rs1 += __shfl_xor_sync(0xffffffffu, rs1, 2);
        l0 = l0 * c0 + rs0;
        l1 = l1 * c1 + rs1;
#pragma unroll
        for (int nt = 0; nt < 8; nt++) {
            O[nt][0] *= c0; O[nt][1] *= c0;
            O[nt][2] *= c1; O[nt][3] *= c1;
        }

        // pending: V(t), K(t+1), V(t+1). Wait V(t).
        CP_WAITG(2);
        __syncthreads();

        // ---- O += P V (3-pass split), V frags via ldmatrix.trans
#pragma unroll
        for (int ks = 0; ks < 4; ks++) {
            uint32_t vf[8][2];
            int kvrow = ks * 16 + (lane & 15);
            uint32_t rsw = kvrow * 128;
#pragma unroll
            for (int p = 0; p < 4; p++) {
                int dseg = 2 * p + (lane >> 4);
                uint32_t addr = stg + 16384 + rsw + ((dseg ^ (kvrow & 7)) << 4);
                ldsm4t(&vf[2 * p][0], addr);
            }
#pragma unroll
            for (int nt = 0; nt < 8; nt++) {
                mma16816(O[nt], aPh[ks], vf[nt]);
                mma16816(O[nt], aPl[ks], vf[nt]);
            }
#pragma unroll
            for (int p = 0; p < 4; p++) {
                int dseg = 2 * p + (lane >> 4);
                uint32_t addr = stg + 24576 + rsw + ((dseg ^ (kvrow & 7)) << 4);
                ldsm4t(&vf[2 * p][0], addr);
            }
#pragma unroll
            for (int nt = 0; nt < 8; nt++)
                mma16816(O[nt], aPh[ks], vf[nt]);
        }
    }

    // ---- normalize + write out[b][l][h*64+d]
    float i0 = 1.f / l0, i1 = 1.f / l1;
    size_t r0 = (size_t)(b * LL + qb + wm + gid);
#pragma unroll
    for (int nt = 0; nt < 8; nt++) {
        int d = h * HDIM + nt * 8 + 2 * tg;
        *(float2*)(out + r0 * DD + d) = make_float2(O[nt][0] * i0, O[nt][1] * i0);
        *(float2*)(out + (r0 + 8) * DD + d) = make_float2(O[nt][2] * i1, O[nt][3] * i1);
    }
}

// ---------------------------------------------------------------------------
extern "C" void kernel_launch(void* const* d_in, const int* in_sizes, int n_in,
                              void* d_out, int out_size)
{
    const float* x    = (const float*)d_in[0];
    const float* w_in = (const float*)d_in[1];
    const float* off  = (const float*)d_in[2];
    const float* amp  = (const float*)d_in[3];
    const float* shp  = (const float*)d_in[4];
    float* out = (float*)d_out;

    scores_kernel<<<dim3(HH, 8), 256>>>(off, amp, shp);

    convert2_kernel<<<MTOT + D3, 256>>>(x, w_in);

    {
        const int smem_bytes = 3 * PSTG;  // 98304
        cudaFuncSetAttribute(proj_mma, cudaFuncAttributeMaxDynamicSharedMemorySize,
                             smem_bytes);
        dim3 grid(D3 / 128, MTOT / 128);
        proj_mma<<<grid, 256, smem_bytes>>>();
    }

    {
        const int smem_bytes = 98304 + 2 * 192 * 4;  // 99840
        cudaFuncSetAttribute(attn_mma, cudaFuncAttributeMaxDynamicSharedMemorySize,
                             smem_bytes);
        dim3 agrid(LL / 128, HH, BB);
        attn_mma<<<agrid, 256, smem_bytes>>>(out);
    }
}

// round 10
// speedup vs baseline: 1.0052x; 1.0052x over previous
#include <cuda_runtime.h>
#include <cuda_bf16.h>
#include <math.h>
#include <stdint.h>

#define BB 2
#define LL 2048
#define DD 1024
#define HH 16
#define HDIM 64
#define D3 3072
#define RLEN 4095   // 2*L - 1
#define MTOT 4096   // B*L
#define K2 2048     // hi|lo concatenated K

// Scratch (no allocation allowed)
__device__ float g_scores[HH * RLEN];
__device__ __align__(1024) __nv_bfloat16 g_Abig[(size_t)MTOT * K2];  // x  hi|lo
__device__ __align__(1024) __nv_bfloat16 g_Bbig[(size_t)D3 * K2];    // w  hi|lo
// Per-head bf16 hi/lo tensors: [b][h][l][64]
#define HSZ ((size_t)BB * HH * LL * HDIM)
__device__ __align__(1024) __nv_bfloat16 g_Qh[HSZ];
__device__ __align__(1024) __nv_bfloat16 g_Ql[HSZ];
__device__ __align__(1024) __nv_bfloat16 g_Kh[HSZ];
__device__ __align__(1024) __nv_bfloat16 g_Kl[HSZ];
__device__ __align__(1024) __nv_bfloat16 g_Vh[HSZ];
__device__ __align__(1024) __nv_bfloat16 g_Vl[HSZ];

__device__ __forceinline__ uint32_t smem_to_u32(const void* p) {
    uint32_t a;
    asm("{ .reg .u64 t; cvta.to.shared.u64 t, %1; cvt.u32.u64 %0, t; }"
        : "=r"(a) : "l"(p));
    return a;
}
#define CP16(dst, src) \
    asm volatile("cp.async.cg.shared.global [%0], [%1], 16;" :: "r"(dst), "l"(src))
#define CP_COMMIT() asm volatile("cp.async.commit_group;" ::: "memory")
#define CP_WAITG(n) asm volatile("cp.async.wait_group %0;" :: "n"(n) : "memory")

__device__ __forceinline__ void ldsm4(uint32_t* r, uint32_t addr) {
    asm volatile("ldmatrix.sync.aligned.m8n8.x4.shared.b16 {%0, %1, %2, %3}, [%4];"
                 : "=r"(r[0]), "=r"(r[1]), "=r"(r[2]), "=r"(r[3]) : "r"(addr));
}
__device__ __forceinline__ void ldsm4t(uint32_t* r, uint32_t addr) {
    asm volatile("ldmatrix.sync.aligned.m8n8.x4.trans.shared.b16 {%0, %1, %2, %3}, [%4];"
                 : "=r"(r[0]), "=r"(r[1]), "=r"(r[2]), "=r"(r[3]) : "r"(addr));
}
__device__ __forceinline__ void mma16816(float* c, const uint32_t* a, const uint32_t* b) {
    asm volatile("mma.sync.aligned.m16n8k16.row.col.f32.bf16.bf16.f32 "
                 "{%0, %1, %2, %3}, {%4, %5, %6, %7}, {%8, %9}, {%0, %1, %2, %3};"
                 : "+f"(c[0]), "+f"(c[1]), "+f"(c[2]), "+f"(c[3])
                 : "r"(a[0]), "r"(a[1]), "r"(a[2]), "r"(a[3]), "r"(b[0]), "r"(b[1]));
}
// packed bf16x2: low = lo, high = hi
__device__ __forceinline__ uint32_t packbf(float lo, float hi) {
    uint32_t r;
    asm("cvt.rn.bf16x2.f32 %0, %1, %2;" : "=r"(r) : "f"(hi), "f"(lo));
    return r;
}

// ---------------------------------------------------------------------------
// Kernel 1: fused fp32 -> bf16 hi/lo split for x and w_in, PLUS the TISA bias
// table as 128 tail blocks (one launch total).
// ---------------------------------------------------------------------------
__global__ __launch_bounds__(256) void convert2_kernel(const float* __restrict__ x,
                                                       const float* __restrict__ w,
                                                       const float* __restrict__ off,
                                                       const float* __restrict__ amp,
                                                       const float* __restrict__ shp)
{
    __shared__ float so[16], sa[16], ss[16];
    int blk = blockIdx.x;
    if (blk >= MTOT + D3) {
        // ---- scores path: blk-(MTOT+D3) = h*8 + slice
        int b2 = blk - (MTOT + D3);
        int h = b2 >> 3, slice = b2 & 7;
        if (threadIdx.x < 16) {
            so[threadIdx.x] = off[h * 16 + threadIdx.x];
            sa[threadIdx.x] = amp[h * 16 + threadIdx.x];
            ss[threadIdx.x] = fabsf(shp[h * 16 + threadIdx.x]);
        }
        __syncthreads();
        for (int r = slice * 256 + threadIdx.x; r < RLEN; r += 8 * 256) {
            float rel = (float)(r - (LL - 1));
            float acc = 0.f;
#pragma unroll
            for (int k = 0; k < 16; k++) {
                float d = so[k] - rel;
                acc += sa[k] * expf(-ss[k] * d * d);
            }
            g_scores[h * RLEN + r] = acc;
        }
        return;
    }

    // ---- convert path
    int idx = blk * 256 + threadIdx.x;
    int row = idx >> 8;
    int k = (idx & 255) << 2;
    const float* src;
    __nv_bfloat16* dst;
    int r;
    if (row < MTOT) { src = x; dst = g_Abig; r = row; }
    else            { src = w; dst = g_Bbig; r = row - MTOT; }
    float4 v = *(const float4*)(src + (size_t)r * DD + k);
    __nv_bfloat16 h0 = __float2bfloat16_rn(v.x);
    __nv_bfloat16 h1 = __float2bfloat16_rn(v.y);
    __nv_bfloat16 h2 = __float2bfloat16_rn(v.z);
    __nv_bfloat16 h3 = __float2bfloat16_rn(v.w);
    __nv_bfloat16 l0 = __float2bfloat16_rn(v.x - __bfloat162float(h0));
    __nv_bfloat16 l1 = __float2bfloat16_rn(v.y - __bfloat162float(h1));
    __nv_bfloat16 l2 = __float2bfloat16_rn(v.z - __bfloat162float(h2));
    __nv_bfloat16 l3 = __float2bfloat16_rn(v.w - __bfloat162float(h3));
    __nv_bfloat162* dh = (__nv_bfloat162*)(dst + (size_t)r * K2 + k);
    dh[0] = __nv_bfloat162(h0, h1);
    dh[1] = __nv_bfloat162(h2, h3);
    __nv_bfloat162* dl = (__nv_bfloat162*)(dst + (size_t)r * K2 + DD + k);
    dl[0] = __nv_bfloat162(l0, l1);
    dl[1] = __nv_bfloat162(l2, l3);
}

// ---------------------------------------------------------------------------
// Kernel 2: HMMA split GEMM (R7 structure — known-good register budget).
// CTA 128x128, 8 warps (4M x 2N), warp tile 32x64, BK=64, 3-stage cp.async.
// 48 chunks: 16x Ahi*Bhi, 16x Ahi*Blo, 16x Alo*Bhi. 2 CTAs/SM.
// Single barrier per chunk (the trailing one was redundant: the next
// iteration's leading barrier protects stage reuse).
// ---------------------------------------------------------------------------
#define NCHUNK 48
#define STG_BYTES 32768

__device__ __forceinline__ void load_chunk(uint32_t sA, uint32_t sB,
                                           const __nv_bfloat16* __restrict__ gA,
                                           const __nv_bfloat16* __restrict__ gB,
                                           int bm, int bn, int ka, int kb, int tid)
{
#pragma unroll
    for (int i = 0; i < 4; i++) {
        int s = tid + i * 256;
        int row = s >> 3, kseg = s & 7;
        uint32_t dst = sA + row * 128 + ((kseg ^ (row & 7)) << 4);
        const void* src = gA + (size_t)(bm + row) * K2 + ka + kseg * 8;
        CP16(dst, src);
    }
#pragma unroll
    for (int i = 0; i < 4; i++) {
        int s = tid + i * 256;
        int row = s >> 3, kseg = s & 7;
        uint32_t dst = sB + row * 128 + ((kseg ^ (row & 7)) << 4);
        const void* src = gB + (size_t)(bn + row) * K2 + kb + kseg * 8;
        CP16(dst, src);
    }
    CP_COMMIT();
}

__global__ __launch_bounds__(256, 2) void proj_mma()
{
    extern __shared__ char smem[];
    const uint32_t sbase = smem_to_u32(smem);
    const int tid = threadIdx.x;
    const int wid = tid >> 5, lane = tid & 31;
    const int bm = blockIdx.y * 128, bn = blockIdx.x * 128;
    const int wm = (wid >> 1) * 32;
    const int wn = (wid & 1) * 64;

    float acc[2][8][4];
#pragma unroll
    for (int mt = 0; mt < 2; mt++)
#pragma unroll
        for (int nt = 0; nt < 8; nt++)
#pragma unroll
            for (int c = 0; c < 4; c++) acc[mt][nt][c] = 0.f;

    auto kamap = [](int t, int& ka, int& kb) {
        int pass = t >> 4, kt = t & 15;
        ka = (pass == 2) ? (DD + kt * 64) : (kt * 64);
        kb = (pass == 1) ? (DD + kt * 64) : (kt * 64);
    };

    {
        int ka, kb;
        kamap(0, ka, kb);
        load_chunk(sbase, sbase + 16384, g_Abig, g_Bbig, bm, bn, ka, kb, tid);
        kamap(1, ka, kb);
        load_chunk(sbase + STG_BYTES, sbase + STG_BYTES + 16384, g_Abig, g_Bbig,
                   bm, bn, ka, kb, tid);
    }

    for (int t = 0; t < NCHUNK; t++) {
        CP_WAITG(1);
        __syncthreads();   // stage t ready for ALL warps; also protects the
                           // stage this iteration's load will overwrite
        if (t + 2 < NCHUNK) {
            int ka, kb;
            kamap(t + 2, ka, kb);
            uint32_t s = sbase + ((t + 2) % 3) * STG_BYTES;
            load_chunk(s, s + 16384, g_Abig, g_Bbig, bm, bn, ka, kb, tid);
        } else {
            CP_COMMIT();
        }

        const uint32_t sA = sbase + (t % 3) * STG_BYTES;
        const uint32_t sB = sA + 16384;

#pragma unroll
        for (int kk = 0; kk < 4; kk++) {
            uint32_t a[2][4];
#pragma unroll
            for (int mt = 0; mt < 2; mt++) {
                int row = wm + mt * 16 + (lane & 15);
                int kseg = kk * 2 + (lane >> 4);
                uint32_t addr = sA + row * 128 + ((kseg ^ (row & 7)) << 4);
                ldsm4(a[mt], addr);
            }
            uint32_t b[8][2];
#pragma unroll
            for (int p = 0; p < 4; p++) {
                int row = wn + p * 16 + (lane & 7) + ((lane >> 4) << 3);
                int kseg = kk * 2 + ((lane >> 3) & 1);
                uint32_t addr = sB + row * 128 + ((kseg ^ (row & 7)) << 4);
                ldsm4(&b[2 * p][0], addr);
            }
#pragma unroll
            for (int mt = 0; mt < 2; mt++)
#pragma unroll
                for (int nt = 0; nt < 8; nt++)
                    mma16816(acc[mt][nt], a[mt], b[nt]);
        }
        // no trailing barrier: next iteration's leading barrier protects reuse
    }

    // Epilogue: split each value into bf16 hi/lo, write to per-head q/k/v arrays.
#pragma unroll
    for (int mt = 0; mt < 2; mt++) {
        int row0 = bm + wm + mt * 16 + (lane >> 2);
        int b = row0 >> 11;
        int l = row0 & 2047;
#pragma unroll
        for (int nt = 0; nt < 8; nt++) {
            int col = bn + wn + nt * 8 + (lane & 3) * 2;
            int ty = col >> 10;            // 0=k, 1=v, 2=q
            int h = (col >> 6) & 15;
            int d = col & 63;
            float sc = (ty == 2) ? 0.125f : 1.0f;
            float v0 = acc[mt][nt][0] * sc, v1 = acc[mt][nt][1] * sc;
            float v2 = acc[mt][nt][2] * sc, v3 = acc[mt][nt][3] * sc;
            uint32_t h01 = packbf(v0, v1), h23 = packbf(v2, v3);
            uint32_t l01 = packbf(v0 - __uint_as_float(h01 << 16),
                                  v1 - __uint_as_float(h01 & 0xFFFF0000u));
            uint32_t l23 = packbf(v2 - __uint_as_float(h23 << 16),
                                  v3 - __uint_as_float(h23 & 0xFFFF0000u));
            __nv_bfloat16 *dh, *dl;
            if (ty == 0)      { dh = g_Kh; dl = g_Kl; }
            else if (ty == 1) { dh = g_Vh; dl = g_Vl; }
            else              { dh = g_Qh; dl = g_Ql; }
            size_t base0 = ((size_t)(b * HH + h) * LL + l) * HDIM + d;
            size_t base1 = base0 + 8 * HDIM;
            *(uint32_t*)(dh + base0) = h01;
            *(uint32_t*)(dl + base0) = l01;
            *(uint32_t*)(dh + base1) = h23;
            *(uint32_t*)(dl + base1) = l23;
        }
    }
}

// ---------------------------------------------------------------------------
// Kernel 3: HMMA flash attention, hi/lo split, 2 CTAs/SM. (R7, unchanged)
// smem: KV stage s at s*32768 (Khi|Klo|Vhi|Vlo, 8KB each);
//       Q dedicated @65536 (hi 16KB, lo 16KB); bias sb[2][192] @98304.
// ---------------------------------------------------------------------------
__device__ __forceinline__ void attn_load_k(uint32_t sbase, int stage, int bh,
                                            int kb, int tid)
{
    uint32_t stg = sbase + stage * 32768;
#pragma unroll
    for (int i = 0; i < 4; i++) {
        const int comp = i >> 1;           // 0=Khi 1=Klo
        int row = (tid >> 3) + 32 * (i & 1);
        int kseg = tid & 7;
        const __nv_bfloat16* gb = comp ? g_Kl : g_Kh;
        uint32_t dst = stg + comp * 8192 + row * 128 + ((kseg ^ (row & 7)) << 4);
        const void* src = gb + ((size_t)bh * LL + kb + row) * HDIM + kseg * 8;
        CP16(dst, src);
    }
    CP_COMMIT();
}
__device__ __forceinline__ void attn_load_v(uint32_t sbase, int stage, int bh,
                                            int kb, int tid)
{
    uint32_t stg = sbase + stage * 32768 + 16384;
#pragma unroll
    for (int i = 0; i < 4; i++) {
        const int comp = i >> 1;           // 0=Vhi 1=Vlo
        int row = (tid >> 3) + 32 * (i & 1);
        int kseg = tid & 7;
        const __nv_bfloat16* gb = comp ? g_Vl : g_Vh;
        uint32_t dst = stg + comp * 8192 + row * 128 + ((kseg ^ (row & 7)) << 4);
        const void* src = gb + ((size_t)bh * LL + kb + row) * HDIM + kseg * 8;
        CP16(dst, src);
    }
    CP_COMMIT();
}

__global__ __launch_bounds__(256, 2) void attn_mma(float* __restrict__ out)
{
    extern __shared__ char smem[];
    const uint32_t sbase = smem_to_u32(smem);
    const uint32_t sQ = sbase + 65536;     // Q hi @ +0, Q lo @ +16384
    float* sb = (float*)(smem + 98304);    // [2][192]
    const int tid = threadIdx.x;
    const int wid = tid >> 5, lane = tid & 31;
    const int gid = lane >> 2, tg = lane & 3;
    const int qb = blockIdx.x * 128;
    const int h = blockIdx.y, b = blockIdx.z;
    const int bh = b * HH + h;
    const int wm = wid * 16;
    const float* srow = g_scores + h * RLEN;

    // --- Prologue: Q (hi/lo) into dedicated smem; K0/V0 issued right behind.
#pragma unroll
    for (int i = 0; i < 8; i++) {
        const int comp = i >> 2;
        int row = (tid >> 3) + 32 * (i & 3);
        int kseg = tid & 7;
        const __nv_bfloat16* gb = comp ? g_Ql : g_Qh;
        uint32_t dst = sQ + comp * 16384 + row * 128 + ((kseg ^ (row & 7)) << 4);
        const void* src = gb + ((size_t)bh * LL + qb + row) * HDIM + kseg * 8;
        CP16(dst, src);
    }
    CP_COMMIT();                         // group: Q
    attn_load_k(sbase, 0, bh, 0, tid);   // group: K0
    attn_load_v(sbase, 0, bh, 0, tid);   // group: V0
    if (tid < 192) {
        int sidx = qb + 1984 + tid;
        sb[tid] = srow[min(sidx, RLEN - 1)];
    }
    CP_WAITG(2);                         // Q done (K0/V0 may be pending)
    __syncthreads();

    uint32_t aQh[4][4];
#pragma unroll
    for (int ks = 0; ks < 4; ks++) {
        int row = wm + (lane & 15);
        int kseg = ks * 2 + (lane >> 4);
        ldsm4(aQh[ks], sQ + row * 128 + ((kseg ^ (row & 7)) << 4));
    }

    float O[8][4];
#pragma unroll
    for (int nt = 0; nt < 8; nt++)
#pragma unroll
        for (int c = 0; c < 4; c++) O[nt][c] = 0.f;
    float m0 = -1e30f, m1 = -1e30f, l0 = 0.f, l1 = 0.f;

    for (int t = 0; t < LL / 64; t++) {
        // pending here: K(t), V(t). Wait K only.
        CP_WAITG(1);
        __syncthreads();
        const uint32_t stg = sbase + (t & 1) * 32768;
        const float* sbt = sb + (t & 1) * 192;

        if (t + 1 < LL / 64) {
            attn_load_k(sbase, (t + 1) & 1, bh, (t + 1) * 64, tid);
            attn_load_v(sbase, (t + 1) & 1, bh, (t + 1) * 64, tid);
            if (tid < 192) {
                int sidx = qb - (t + 1) * 64 + 1984 + tid;
                sb[((t + 1) & 1) * 192 + tid] = srow[min(sidx, RLEN - 1)];
            }
        } else {
            CP_COMMIT();
            CP_COMMIT();
        }

        // ---- S = Q K^T (3-pass split), fp32 accum
        float S[8][4];
#pragma unroll
        for (int nt = 0; nt < 8; nt++)
#pragma unroll
            for (int c = 0; c < 4; c++) S[nt][c] = 0.f;

#pragma unroll
        for (int kk = 0; kk < 4; kk++) {
            // Q-lo fragment for this k-step (from dedicated smem)
            uint32_t aQl[4];
            {
                int row = wm + (lane & 15);
                int kseg = kk * 2 + (lane >> 4);
                ldsm4(aQl, sQ + 16384 + row * 128 + ((kseg ^ (row & 7)) << 4));
            }
            uint32_t kf[8][2];
            int krow = (lane & 7) + ((lane >> 4) << 3);
            int kkseg = kk * 2 + ((lane >> 3) & 1);
#pragma unroll
            for (int p = 0; p < 4; p++) {
                int row = krow + p * 16;
                uint32_t addr = stg + row * 128 + ((kkseg ^ (row & 7)) << 4);
                ldsm4(&kf[2 * p][0], addr);
            }
#pragma unroll
            for (int nt = 0; nt < 8; nt++) {
                mma16816(S[nt], aQh[kk], kf[nt]);
                mma16816(S[nt], aQl, kf[nt]);
            }
#pragma unroll
            for (int p = 0; p < 4; p++) {
                int row = krow + p * 16;
                uint32_t addr = stg + 8192 + row * 128 + ((kkseg ^ (row & 7)) << 4);
                ldsm4(&kf[2 * p][0], addr);
            }
#pragma unroll
            for (int nt = 0; nt < 8; nt++)
                mma16816(S[nt], aQh[kk], kf[nt]);
        }

        // ---- bias + online softmax (V load still in flight underneath)
        const int jbase = wm + gid + 63 - 2 * tg;
        float mx0 = -1e30f, mx1 = -1e30f;
#pragma unroll
        for (int nt = 0; nt < 8; nt++) {
            int j = jbase - 8 * nt;
            S[nt][0] += sbt[j];
            S[nt][1] += sbt[j - 1];
            S[nt][2] += sbt[j + 8];
            S[nt][3] += sbt[j + 7];
            mx0 = fmaxf(mx0, fmaxf(S[nt][0], S[nt][1]));
            mx1 = fmaxf(mx1, fmaxf(S[nt][2], S[nt][3]));
        }
        mx0 = fmaxf(mx0, __shfl_xor_sync(0xffffffffu, mx0, 1));
        mx0 = fmaxf(mx0, __shfl_xor_sync(0xffffffffu, mx0, 2));
        mx1 = fmaxf(mx1, __shfl_xor_sync(0xffffffffu, mx1, 1));
        mx1 = fmaxf(mx1, __shfl_xor_sync(0xffffffffu, mx1, 2));
        float nm0 = fmaxf(m0, mx0), nm1 = fmaxf(m1, mx1);
        float c0 = __expf(m0 - nm0), c1 = __expf(m1 - nm1);
        m0 = nm0; m1 = nm1;

        float rs0 = 0.f, rs1 = 0.f;
        uint32_t aPh[4][4], aPl[4][4];
#pragma unroll
        for (int nt = 0; nt < 8; nt++) {
            float p0 = __expf(S[nt][0] - nm0);
            float p1 = __expf(S[nt][1] - nm0);
            float p2 = __expf(S[nt][2] - nm1);
            float p3 = __expf(S[nt][3] - nm1);
            rs0 += p0 + p1;
            rs1 += p2 + p3;
            uint32_t h01 = packbf(p0, p1), h23 = packbf(p2, p3);
            uint32_t l01 = packbf(p0 - __uint_as_float(h01 << 16),
                                  p1 - __uint_as_float(h01 & 0xFFFF0000u));
            uint32_t l23 = packbf(p2 - __uint_as_float(h23 << 16),
                                  p3 - __uint_as_float(h23 & 0xFFFF0000u));
            int ks = nt >> 1, hf = (nt & 1) * 2;
            aPh[ks][hf] = h01; aPh[ks][hf + 1] = h23;
            aPl[ks][hf] = l01; aPl[ks][hf + 1] = l23;
        }
        rs0 += __shfl_xor_sync(0xffffffffu, rs0, 1);
        rs0 += __shfl_xor_sync(0xffffffffu, rs0, 2);
        rs1 += __shfl_xor_sync(0xffffffffu, rs1, 1);
        rs1 += __shfl_xor_sync(0xffffffffu, rs1, 2);
        l0 = l0 * c0 + rs0;
        l1 = l1 * c1 + rs1;
#pragma unroll
        for (int nt = 0; nt < 8; nt++) {
            O[nt][0] *= c0; O[nt][1] *= c0;
            O[nt][2] *= c1; O[nt][3] *= c1;
        }

        // pending: V(t), K(t+1), V(t+1). Wait V(t).
        CP_WAITG(2);
        __syncthreads();

        // ---- O += P V (3-pass split), V frags via ldmatrix.trans
#pragma unroll
        for (int ks = 0; ks < 4; ks++) {
            uint32_t vf[8][2];
            int kvrow = ks * 16 + (lane & 15);
            uint32_t rsw = kvrow * 128;
#pragma unroll
            for (int p = 0; p < 4; p++) {
                int dseg = 2 * p + (lane >> 4);
                uint32_t addr = stg + 16384 + rsw + ((dseg ^ (kvrow & 7)) << 4);
                ldsm4t(&vf[2 * p][0], addr);
            }
#pragma unroll
            for (int nt = 0; nt < 8; nt++) {
                mma16816(O[nt], aPh[ks], vf[nt]);
                mma16816(O[nt], aPl[ks], vf[nt]);
            }
#pragma unroll
            for (int p = 0; p < 4; p++) {
                int dseg = 2 * p + (lane >> 4);
                uint32_t addr = stg + 24576 + rsw + ((dseg ^ (kvrow & 7)) << 4);
                ldsm4t(&vf[2 * p][0], addr);
            }
#pragma unroll
            for (int nt = 0; nt < 8; nt++)
                mma16816(O[nt], aPh[ks], vf[nt]);
        }
    }

    // ---- normalize + write out[b][l][h*64+d]
    float i0 = 1.f / l0, i1 = 1.f / l1;
    size_t r0 = (size_t)(b * LL + qb + wm + gid);
#pragma unroll
    for (int nt = 0; nt < 8; nt++) {
        int d = h * HDIM + nt * 8 + 2 * tg;
        *(float2*)(out + r0 * DD + d) = make_float2(O[nt][0] * i0, O[nt][1] * i0);
        *(float2*)(out + (r0 + 8) * DD + d) = make_float2(O[nt][2] * i1, O[nt][3] * i1);
    }
}

// ---------------------------------------------------------------------------
extern "C" void kernel_launch(void* const* d_in, const int* in_sizes, int n_in,
                              void* d_out, int out_size)
{
    const float* x    = (const float*)d_in[0];
    const float* w_in = (const float*)d_in[1];
    const float* off  = (const float*)d_in[2];
    const float* amp  = (const float*)d_in[3];
    const float* shp  = (const float*)d_in[4];
    float* out = (float*)d_out;

    // converts + scores in one launch (scores ride as 128 tail blocks)
    convert2_kernel<<<MTOT + D3 + HH * 8, 256>>>(x, w_in, off, amp, shp);

    {
        const int smem_bytes = 3 * STG_BYTES;  // 98304
        cudaFuncSetAttribute(proj_mma, cudaFuncAttributeMaxDynamicSharedMemorySize,
                             smem_bytes);
        dim3 grid(D3 / 128, MTOT / 128);
        proj_mma<<<grid, 256, smem_bytes>>>();
    }

    {
        const int smem_bytes = 98304 + 2 * 192 * 4;  // 99840
        cudaFuncSetAttribute(attn_mma, cudaFuncAttributeMaxDynamicSharedMemorySize,
                             smem_bytes);
        dim3 agrid(LL / 128, HH, BB);
        attn_mma<<<agrid, 256, smem_bytes>>>(out);
    }
}

// round 12
// speedup vs baseline: 1.5410x; 1.5330x over previous
#include <cuda_runtime.h>
#include <cuda_bf16.h>
#include <math.h>
#include <stdint.h>

#define BB 2
#define LL 2048
#define DD 1024
#define HH 16
#define HDIM 64
#define D3 3072
#define RLEN 4095   // 2*L - 1
#define MTOT 4096   // B*L
#define K2 2048     // hi|lo concatenated K

// Scratch (no allocation allowed)
__device__ float g_scores[HH * RLEN];
__device__ __align__(1024) __nv_bfloat16 g_Abig[(size_t)MTOT * K2];  // x  hi|lo
__device__ __align__(1024) __nv_bfloat16 g_Bbig[(size_t)D3 * K2];    // w  hi|lo
// Per-head bf16 hi/lo tensors: [b][h][l][64]
#define HSZ ((size_t)BB * HH * LL * HDIM)
__device__ __align__(1024) __nv_bfloat16 g_Qh[HSZ];
__device__ __align__(1024) __nv_bfloat16 g_Ql[HSZ];
__device__ __align__(1024) __nv_bfloat16 g_Kh[HSZ];
__device__ __align__(1024) __nv_bfloat16 g_Kl[HSZ];
__device__ __align__(1024) __nv_bfloat16 g_Vh[HSZ];
__device__ __align__(1024) __nv_bfloat16 g_Vl[HSZ];

__device__ __forceinline__ uint32_t smem_to_u32(const void* p) {
    uint32_t a;
    asm("{ .reg .u64 t; cvta.to.shared.u64 t, %1; cvt.u32.u64 %0, t; }"
        : "=r"(a) : "l"(p));
    return a;
}
#define CP16(dst, src) \
    asm volatile("cp.async.cg.shared.global [%0], [%1], 16;" :: "r"(dst), "l"(src))
#define CP_COMMIT() asm volatile("cp.async.commit_group;" ::: "memory")
#define CP_WAITG(n) asm volatile("cp.async.wait_group %0;" :: "n"(n) : "memory")

__device__ __forceinline__ void ldsm4(uint32_t* r, uint32_t addr) {
    asm volatile("ldmatrix.sync.aligned.m8n8.x4.shared.b16 {%0, %1, %2, %3}, [%4];"
                 : "=r"(r[0]), "=r"(r[1]), "=r"(r[2]), "=r"(r[3]) : "r"(addr));
}
__device__ __forceinline__ void ldsm4t(uint32_t* r, uint32_t addr) {
    asm volatile("ldmatrix.sync.aligned.m8n8.x4.trans.shared.b16 {%0, %1, %2, %3}, [%4];"
                 : "=r"(r[0]), "=r"(r[1]), "=r"(r[2]), "=r"(r[3]) : "r"(addr));
}
__device__ __forceinline__ void mma16816(float* c, const uint32_t* a, const uint32_t* b) {
    asm volatile("mma.sync.aligned.m16n8k16.row.col.f32.bf16.bf16.f32 "
                 "{%0, %1, %2, %3}, {%4, %5, %6, %7}, {%8, %9}, {%0, %1, %2, %3};"
                 : "+f"(c[0]), "+f"(c[1]), "+f"(c[2]), "+f"(c[3])
                 : "r"(a[0]), "r"(a[1]), "r"(a[2]), "r"(a[3]), "r"(b[0]), "r"(b[1]));
}
// packed bf16x2: low = lo, high = hi
__device__ __forceinline__ uint32_t packbf(float lo, float hi) {
    uint32_t r;
    asm("cvt.rn.bf16x2.f32 %0, %1, %2;" : "=r"(r) : "f"(hi), "f"(lo));
    return r;
}

// ---------------------------------------------------------------------------
// Kernel 1: fused fp32 -> bf16 hi/lo split for x and w_in, PLUS the TISA bias
// table as 128 tail blocks (one launch total). Measured 20.5us in R9 — keep.
// ---------------------------------------------------------------------------
__global__ __launch_bounds__(256) void convert2_kernel(const float* __restrict__ x,
                                                       const float* __restrict__ w,
                                                       const float* __restrict__ off,
                                                       const float* __restrict__ amp,
                                                       const float* __restrict__ shp)
{
    __shared__ float so[16], sa[16], ss[16];
    int blk = blockIdx.x;
    if (blk >= MTOT + D3) {
        // ---- scores path: blk-(MTOT+D3) = h*8 + slice
        int b2 = blk - (MTOT + D3);
        int h = b2 >> 3, slice = b2 & 7;
        if (threadIdx.x < 16) {
            so[threadIdx.x] = off[h * 16 + threadIdx.x];
            sa[threadIdx.x] = amp[h * 16 + threadIdx.x];
            ss[threadIdx.x] = fabsf(shp[h * 16 + threadIdx.x]);
        }
        __syncthreads();
        for (int r = slice * 256 + threadIdx.x; r < RLEN; r += 8 * 256) {
            float rel = (float)(r - (LL - 1));
            float acc = 0.f;
#pragma unroll
            for (int k = 0; k < 16; k++) {
                float d = so[k] - rel;
                acc += sa[k] * expf(-ss[k] * d * d);
            }
            g_scores[h * RLEN + r] = acc;
        }
        return;
    }

    // ---- convert path
    int idx = blk * 256 + threadIdx.x;
    int row = idx >> 8;
    int k = (idx & 255) << 2;
    const float* src;
    __nv_bfloat16* dst;
    int r;
    if (row < MTOT) { src = x; dst = g_Abig; r = row; }
    else            { src = w; dst = g_Bbig; r = row - MTOT; }
    float4 v = *(const float4*)(src + (size_t)r * DD + k);
    __nv_bfloat16 h0 = __float2bfloat16_rn(v.x);
    __nv_bfloat16 h1 = __float2bfloat16_rn(v.y);
    __nv_bfloat16 h2 = __float2bfloat16_rn(v.z);
    __nv_bfloat16 h3 = __float2bfloat16_rn(v.w);
    __nv_bfloat16 l0 = __float2bfloat16_rn(v.x - __bfloat162float(h0));
    __nv_bfloat16 l1 = __float2bfloat16_rn(v.y - __bfloat162float(h1));
    __nv_bfloat16 l2 = __float2bfloat16_rn(v.z - __bfloat162float(h2));
    __nv_bfloat16 l3 = __float2bfloat16_rn(v.w - __bfloat162float(h3));
    __nv_bfloat162* dh = (__nv_bfloat162*)(dst + (size_t)r * K2 + k);
    dh[0] = __nv_bfloat162(h0, h1);
    dh[1] = __nv_bfloat162(h2, h3);
    __nv_bfloat162* dl = (__nv_bfloat162*)(dst + (size_t)r * K2 + DD + k);
    dl[0] = __nv_bfloat162(l0, l1);
    dl[1] = __nv_bfloat162(l2, l3);
}

// ---------------------------------------------------------------------------
// Kernel 2: HMMA split GEMM — EXACT R7 structure including BOTH barriers.
// The trailing __syncthreads() is load-bearing for register allocation: it
// fences ptxas from pipelining next-iteration ldsm into the MMA block, which
// is what keeps the kernel at <=128 regs for 2 CTAs/SM (R8/R9 regressions).
// ---------------------------------------------------------------------------
#define NCHUNK 48
#define STG_BYTES 32768

__device__ __forceinline__ void load_chunk(uint32_t sA, uint32_t sB,
                                           const __nv_bfloat16* __restrict__ gA,
                                           const __nv_bfloat16* __restrict__ gB,
                                           int bm, int bn, int ka, int kb, int tid)
{
#pragma unroll
    for (int i = 0; i < 4; i++) {
        int s = tid + i * 256;
        int row = s >> 3, kseg = s & 7;
        uint32_t dst = sA + row * 128 + ((kseg ^ (row & 7)) << 4);
        const void* src = gA + (size_t)(bm + row) * K2 + ka + kseg * 8;
        CP16(dst, src);
    }
#pragma unroll
    for (int i = 0; i < 4; i++) {
        int s = tid + i * 256;
        int row = s >> 3, kseg = s & 7;
        uint32_t dst = sB + row * 128 + ((kseg ^ (row & 7)) << 4);
        const void* src = gB + (size_t)(bn + row) * K2 + kb + kseg * 8;
        CP16(dst, src);
    }
    CP_COMMIT();
}

__global__ __launch_bounds__(256, 2) void proj_mma()
{
    extern __shared__ char smem[];
    const uint32_t sbase = smem_to_u32(smem);
    const int tid = threadIdx.x;
    const int wid = tid >> 5, lane = tid & 31;
    const int bm = blockIdx.y * 128, bn = blockIdx.x * 128;
    const int wm = (wid >> 1) * 32;
    const int wn = (wid & 1) * 64;

    float acc[2][8][4];
#pragma unroll
    for (int mt = 0; mt < 2; mt++)
#pragma unroll
        for (int nt = 0; nt < 8; nt++)
#pragma unroll
            for (int c = 0; c < 4; c++) acc[mt][nt][c] = 0.f;

    auto kamap = [](int t, int& ka, int& kb) {
        int pass = t >> 4, kt = t & 15;
        ka = (pass == 2) ? (DD + kt * 64) : (kt * 64);
        kb = (pass == 1) ? (DD + kt * 64) : (kt * 64);
    };

    {
        int ka, kb;
        kamap(0, ka, kb);
        load_chunk(sbase, sbase + 16384, g_Abig, g_Bbig, bm, bn, ka, kb, tid);
        kamap(1, ka, kb);
        load_chunk(sbase + STG_BYTES, sbase + STG_BYTES + 16384, g_Abig, g_Bbig,
                   bm, bn, ka, kb, tid);
    }

    for (int t = 0; t < NCHUNK; t++) {
        CP_WAITG(1);
        __syncthreads();

        if (t + 2 < NCHUNK) {
            int ka, kb;
            kamap(t + 2, ka, kb);
            uint32_t s = sbase + ((t + 2) % 3) * STG_BYTES;
            load_chunk(s, s + 16384, g_Abig, g_Bbig, bm, bn, ka, kb, tid);
        } else {
            CP_COMMIT();
        }

        const uint32_t sA = sbase + (t % 3) * STG_BYTES;
        const uint32_t sB = sA + 16384;

#pragma unroll
        for (int kk = 0; kk < 4; kk++) {
            uint32_t a[2][4];
#pragma unroll
            for (int mt = 0; mt < 2; mt++) {
                int row = wm + mt * 16 + (lane & 15);
                int kseg = kk * 2 + (lane >> 4);
                uint32_t addr = sA + row * 128 + ((kseg ^ (row & 7)) << 4);
                ldsm4(a[mt], addr);
            }
            uint32_t b[8][2];
#pragma unroll
            for (int p = 0; p < 4; p++) {
                int row = wn + p * 16 + (lane & 7) + ((lane >> 4) << 3);
                int kseg = kk * 2 + ((lane >> 3) & 1);
                uint32_t addr = sB + row * 128 + ((kseg ^ (row & 7)) << 4);
                ldsm4(&b[2 * p][0], addr);
            }
#pragma unroll
            for (int mt = 0; mt < 2; mt++)
#pragma unroll
                for (int nt = 0; nt < 8; nt++)
                    mma16816(acc[mt][nt], a[mt], b[nt]);
        }
        __syncthreads();   // load-bearing: fences ptxas pipelining (reg cap)
    }

    // Epilogue: split each value into bf16 hi/lo, write to per-head q/k/v arrays.
#pragma unroll
    for (int mt = 0; mt < 2; mt++) {
        int row0 = bm + wm + mt * 16 + (lane >> 2);
        int b = row0 >> 11;
        int l = row0 & 2047;
#pragma unroll
        for (int nt = 0; nt < 8; nt++) {
            int col = bn + wn + nt * 8 + (lane & 3) * 2;
            int ty = col >> 10;            // 0=k, 1=v, 2=q
            int h = (col >> 6) & 15;
            int d = col & 63;
            float sc = (ty == 2) ? 0.125f : 1.0f;
            float v0 = acc[mt][nt][0] * sc, v1 = acc[mt][nt][1] * sc;
            float v2 = acc[mt][nt][2] * sc, v3 = acc[mt][nt][3] * sc;
            uint32_t h01 = packbf(v0, v1), h23 = packbf(v2, v3);
            uint32_t l01 = packbf(v0 - __uint_as_float(h01 << 16),
                                  v1 - __uint_as_float(h01 & 0xFFFF0000u));
            uint32_t l23 = packbf(v2 - __uint_as_float(h23 << 16),
                                  v3 - __uint_as_float(h23 & 0xFFFF0000u));
            __nv_bfloat16 *dh, *dl;
            if (ty == 0)      { dh = g_Kh; dl = g_Kl; }
            else if (ty == 1) { dh = g_Vh; dl = g_Vl; }
            else              { dh = g_Qh; dl = g_Ql; }
            size_t base0 = ((size_t)(b * HH + h) * LL + l) * HDIM + d;
            size_t base1 = base0 + 8 * HDIM;
            *(uint32_t*)(dh + base0) = h01;
            *(uint32_t*)(dl + base0) = l01;
            *(uint32_t*)(dh + base1) = h23;
            *(uint32_t*)(dl + base1) = l23;
        }
    }
}

// ---------------------------------------------------------------------------
// Kernel 3: HMMA flash attention, hi/lo split, 2 CTAs/SM. (R7, unchanged)
// smem: KV stage s at s*32768 (Khi|Klo|Vhi|Vlo, 8KB each);
//       Q dedicated @65536 (hi 16KB, lo 16KB); bias sb[2][192] @98304.
// ---------------------------------------------------------------------------
__device__ __forceinline__ void attn_load_k(uint32_t sbase, int stage, int bh,
                                            int kb, int tid)
{
    uint32_t stg = sbase + stage * 32768;
#pragma unroll
    for (int i = 0; i < 4; i++) {
        const int comp = i >> 1;           // 0=Khi 1=Klo
        int row = (tid >> 3) + 32 * (i & 1);
        int kseg = tid & 7;
        const __nv_bfloat16* gb = comp ? g_Kl : g_Kh;
        uint32_t dst = stg + comp * 8192 + row * 128 + ((kseg ^ (row & 7)) << 4);
        const void* src = gb + ((size_t)bh * LL + kb + row) * HDIM + kseg * 8;
        CP16(dst, src);
    }
    CP_COMMIT();
}
__device__ __forceinline__ void attn_load_v(uint32_t sbase, int stage, int bh,
                                            int kb, int tid)
{
    uint32_t stg = sbase + stage * 32768 + 16384;
#pragma unroll
    for (int i = 0; i < 4; i++) {
        const int comp = i >> 1;           // 0=Vhi 1=Vlo
        int row = (tid >> 3) + 32 * (i & 1);
        int kseg = tid & 7;
        const __nv_bfloat16* gb = comp ? g_Vl : g_Vh;
        uint32_t dst = stg + comp * 8192 + row * 128 + ((kseg ^ (row & 7)) << 4);
        const void* src = gb + ((size_t)bh * LL + kb + row) * HDIM + kseg * 8;
        CP16(dst, src);
    }
    CP_COMMIT();
}

__global__ __launch_bounds__(256, 2) void attn_mma(float* __restrict__ out)
{
    extern __shared__ char smem[];
    const uint32_t sbase = smem_to_u32(smem);
    const uint32_t sQ = sbase + 65536;     // Q hi @ +0, Q lo @ +16384
    float* sb = (float*)(smem + 98304);    // [2][192]
    const int tid = threadIdx.x;
    const int wid = tid >> 5, lane = tid & 31;
    const int gid = lane >> 2, tg = lane & 3;
    const int qb = blockIdx.x * 128;
    const int h = blockIdx.y, b = blockIdx.z;
    const int bh = b * HH + h;
    const int wm = wid * 16;
    const float* srow = g_scores + h * RLEN;

    // --- Prologue: Q (hi/lo) into dedicated smem; K0/V0 issued right behind.
#pragma unroll
    for (int i = 0; i < 8; i++) {
        const int comp = i >> 2;
        int row = (tid >> 3) + 32 * (i & 3);
        int kseg = tid & 7;
        const __nv_bfloat16* gb = comp ? g_Ql : g_Qh;
        uint32_t dst = sQ + comp * 16384 + row * 128 + ((kseg ^ (row & 7)) << 4);
        const void* src = gb + ((size_t)bh * LL + qb + row) * HDIM + kseg * 8;
        CP16(dst, src);
    }
    CP_COMMIT();                         // group: Q
    attn_load_k(sbase, 0, bh, 0, tid);   // group: K0
    attn_load_v(sbase, 0, bh, 0, tid);   // group: V0
    if (tid < 192) {
        int sidx = qb + 1984 + tid;
        sb[tid] = srow[min(sidx, RLEN - 1)];
    }
    CP_WAITG(2);                         // Q done (K0/V0 may be pending)
    __syncthreads();

    uint32_t aQh[4][4];
#pragma unroll
    for (int ks = 0; ks < 4; ks++) {
        int row = wm + (lane & 15);
        int kseg = ks * 2 + (lane >> 4);
        ldsm4(aQh[ks], sQ + row * 128 + ((kseg ^ (row & 7)) << 4));
    }

    float O[8][4];
#pragma unroll
    for (int nt = 0; nt < 8; nt++)
#pragma unroll
        for (int c = 0; c < 4; c++) O[nt][c] = 0.f;
    float m0 = -1e30f, m1 = -1e30f, l0 = 0.f, l1 = 0.f;

    for (int t = 0; t < LL / 64; t++) {
        // pending here: K(t), V(t). Wait K only.
        CP_WAITG(1);
        __syncthreads();
        const uint32_t stg = sbase + (t & 1) * 32768;
        const float* sbt = sb + (t & 1) * 192;

        if (t + 1 < LL / 64) {
            attn_load_k(sbase, (t + 1) & 1, bh, (t + 1) * 64, tid);
            attn_load_v(sbase, (t + 1) & 1, bh, (t + 1) * 64, tid);
            if (tid < 192) {
                int sidx = qb - (t + 1) * 64 + 1984 + tid;
                sb[((t + 1) & 1) * 192 + tid] = srow[min(sidx, RLEN - 1)];
            }
        } else {
            CP_COMMIT();
            CP_COMMIT();
        }

        // ---- S = Q K^T (3-pass split), fp32 accum
        float S[8][4];
#pragma unroll
        for (int nt = 0; nt < 8; nt++)
#pragma unroll
            for (int c = 0; c < 4; c++) S[nt][c] = 0.f;

#pragma unroll
        for (int kk = 0; kk < 4; kk++) {
            // Q-lo fragment for this k-step (from dedicated smem)
            uint32_t aQl[4];
            {
                int row = wm + (lane & 15);
                int kseg = kk * 2 + (lane >> 4);
                ldsm4(aQl, sQ + 16384 + row * 128 + ((kseg ^ (row & 7)) << 4));
            }
            uint32_t kf[8][2];
            int krow = (lane & 7) + ((lane >> 4) << 3);
            int kkseg = kk * 2 + ((lane >> 3) & 1);
#pragma unroll
            for (int p = 0; p < 4; p++) {
                int row = krow + p * 16;
                uint32_t addr = stg + row * 128 + ((kkseg ^ (row & 7)) << 4);
                ldsm4(&kf[2 * p][0], addr);
            }
#pragma unroll
            for (int nt = 0; nt < 8; nt++) {
                mma16816(S[nt], aQh[kk], kf[nt]);
                mma16816(S[nt], aQl, kf[nt]);
            }
#pragma unroll
            for (int p = 0; p < 4; p++) {
                int row = krow + p * 16;
                uint32_t addr = stg + 8192 + row * 128 + ((kkseg ^ (row & 7)) << 4);
                ldsm4(&kf[2 * p][0], addr);
            }
#pragma unroll
            for (int nt = 0; nt < 8; nt++)
                mma16816(S[nt], aQh[kk], kf[nt]);
        }

        // ---- bias + online softmax (V load still in flight underneath)
        const int jbase = wm + gid + 63 - 2 * tg;
        float mx0 = -1e30f, mx1 = -1e30f;
#pragma unroll
        for (int nt = 0; nt < 8; nt++) {
            int j = jbase - 8 * nt;
            S[nt][0] += sbt[j];
            S[nt][1] += sbt[j - 1];
            S[nt][2] += sbt[j + 8];
            S[nt][3] += sbt[j + 7];
            mx0 = fmaxf(mx0, fmaxf(S[nt][0], S[nt][1]));
            mx1 = fmaxf(mx1, fmaxf(S[nt][2], S[nt][3]));
        }
        mx0 = fmaxf(mx0, __shfl_xor_sync(0xffffffffu, mx0, 1));
        mx0 = fmaxf(mx0, __shfl_xor_sync(0xffffffffu, mx0, 2));
        mx1 = fmaxf(mx1, __shfl_xor_sync(0xffffffffu, mx1, 1));
        mx1 = fmaxf(mx1, __shfl_xor_sync(0xffffffffu, mx1, 2));
        float nm0 = fmaxf(m0, mx0), nm1 = fmaxf(m1, mx1);
        float c0 = __expf(m0 - nm0), c1 = __expf(m1 - nm1);
        m0 = nm0; m1 = nm1;

        float rs0 = 0.f, rs1 = 0.f;
        uint32_t aPh[4][4], aPl[4][4];
#pragma unroll
        for (int nt = 0; nt < 8; nt++) {
            float p0 = __expf(S[nt][0] - nm0);
            float p1 = __expf(S[nt][1] - nm0);
            float p2 = __expf(S[nt][2] - nm1);
            float p3 = __expf(S[nt][3] - nm1);
            rs0 += p0 + p1;
            rs1 += p2 + p3;
            uint32_t h01 = packbf(p0, p1), h23 = packbf(p2, p3);
            uint32_t l01 = packbf(p0 - __uint_as_float(h01 << 16),
                                  p1 - __uint_as_float(h01 & 0xFFFF0000u));
            uint32_t l23 = packbf(p2 - __uint_as_float(h23 << 16),
                                  p3 - __uint_as_float(h23 & 0xFFFF0000u));
            int ks = nt >> 1, hf = (nt & 1) * 2;
            aPh[ks][hf] = h01; aPh[ks][hf + 1] = h23;
            aPl[ks][hf] = l01; aPl[ks][hf + 1] = l23;
        }
        rs0 += __shfl_xor_sync(0xffffffffu, rs0, 1);
        rs0 += __shfl_xor_sync(0xffffffffu, rs0, 2);
        rs1 += __shfl_xor_sync(0xffffffffu, rs1, 1);
        rs1 += __shfl_xor_sync(0xffffffffu, rs1, 2);
        l0 = l0 * c0 + rs0;
        l1 = l1 * c1 + rs1;
#pragma unroll
        for (int nt = 0; nt < 8; nt++) {
            O[nt][0] *= c0; O[nt][1] *= c0;
            O[nt][2] *= c1; O[nt][3] *= c1;
        }

        // pending: V(t), K(t+1), V(t+1). Wait V(t).
        CP_WAITG(2);
        __syncthreads();

        // ---- O += P V (3-pass split), V frags via ldmatrix.trans
#pragma unroll
        for (int ks = 0; ks < 4; ks++) {
            uint32_t vf[8][2];
            int kvrow = ks * 16 + (lane & 15);
            uint32_t rsw = kvrow * 128;
#pragma unroll
            for (int p = 0; p < 4; p++) {
                int dseg = 2 * p + (lane >> 4);
                uint32_t addr = stg + 16384 + rsw + ((dseg ^ (kvrow & 7)) << 4);
                ldsm4t(&vf[2 * p][0], addr);
            }
#pragma unroll
            for (int nt = 0; nt < 8; nt++) {
                mma16816(O[nt], aPh[ks], vf[nt]);
                mma16816(O[nt], aPl[ks], vf[nt]);
            }
#pragma unroll
            for (int p = 0; p < 4; p++) {
                int dseg = 2 * p + (lane >> 4);
                uint32_t addr = stg + 24576 + rsw + ((dseg ^ (kvrow & 7)) << 4);
                ldsm4t(&vf[2 * p][0], addr);
            }
#pragma unroll
            for (int nt = 0; nt < 8; nt++)
                mma16816(O[nt], aPh[ks], vf[nt]);
        }
    }

    // ---- normalize + write out[b][l][h*64+d]
    float i0 = 1.f / l0, i1 = 1.f / l1;
    size_t r0 = (size_t)(b * LL + qb + wm + gid);
#pragma unroll
    for (int nt = 0; nt < 8; nt++) {
        int d = h * HDIM + nt * 8 + 2 * tg;
        *(float2*)(out + r0 * DD + d) = make_float2(O[nt][0] * i0, O[nt][1] * i0);
        *(float2*)(out + (r0 + 8) * DD + d) = make_float2(O[nt][2] * i1, O[nt][3] * i1);
    }
}

// ---------------------------------------------------------------------------
extern "C" void kernel_launch(void* const* d_in, const int* in_sizes, int n_in,
                              void* d_out, int out_size)
{
    const float* x    = (const float*)d_in[0];
    const float* w_in = (const float*)d_in[1];
    const float* off  = (const float*)d_in[2];
    const float* amp  = (const float*)d_in[3];
    const float* shp  = (const float*)d_in[4];
    float* out = (float*)d_out;

    // converts + scores in one launch (scores ride as 128 tail blocks)
    convert2_kernel<<<MTOT + D3 + HH * 8, 256>>>(x, w_in, off, amp, shp);

    {
        const int smem_bytes = 3 * STG_BYTES;  // 98304
        cudaFuncSetAttribute(proj_mma, cudaFuncAttributeMaxDynamicSharedMemorySize,
                             smem_bytes);
        dim3 grid(D3 / 128, MTOT / 128);
        proj_mma<<<grid, 256, smem_bytes>>>();
    }

    {
        const int smem_bytes = 98304 + 2 * 192 * 4;  // 99840
        cudaFuncSetAttribute(attn_mma, cudaFuncAttributeMaxDynamicSharedMemorySize,
                             smem_bytes);
        dim3 agrid(LL / 128, HH, BB);
        attn_mma<<<agrid, 256, smem_bytes>>>(out);
    }
}